// round 6
// baseline (speedup 1.0000x reference)
#include <cuda_runtime.h>
#include <cuda_fp16.h>
#include <cstdint>

// ---------------------------------------------------------------------------
// GCN: out = SpMM(relu(SpMM(X@W1+b1)) @ W2 + b2)
// R6: R4 baseline components restored + coalesced warp-shuffle fused scan +
//     SpMM1/GEMM2 fusion (gather writes the HMMA A-tile directly in smem).
//     H1 and H2 in separate buffers (fused kernel reads H1 globally while
//     producing H2 — in-place would race).
// ---------------------------------------------------------------------------

#define MAX_NODES 100000
#define MAX_EDGES 1600000
#define FEAT 128

__device__ __align__(16) __half g_H1[(size_t)MAX_NODES * FEAT];
__device__ __align__(16) __half g_H2[(size_t)MAX_NODES * FEAT];
__device__ int  g_cnt[MAX_NODES];
__device__ int  g_row_start[MAX_NODES + 1];
__device__ int  g_row_next[MAX_NODES];
__device__ int2 g_edge[MAX_EDGES];

// ---------------------------------------------------------------------------
// CSR build
// ---------------------------------------------------------------------------
__global__ void zero_cnt_kernel(int4* __restrict__ cnt4, int n4)
{
    int i = blockIdx.x * blockDim.x + threadIdx.x;
    if (i < n4) cnt4[i] = make_int4(0, 0, 0, 0);
}

__global__ void hist_kernel(const int* __restrict__ row, int nE, int* __restrict__ cnt)
{
    int i = blockIdx.x * blockDim.x + threadIdx.x;
    if (i < nE) atomicAdd(&cnt[row[i]], 1);
}

// Single-block exclusive scan, coalesced 1024-wide tiles, warp-shuffle scan.
__global__ __launch_bounds__(1024) void scan_fused_kernel(
    const int* __restrict__ cnt, int* __restrict__ row_start,
    int* __restrict__ row_next, int n)
{
    __shared__ int warp_off[32];
    __shared__ int tile_tot;
    const int tid  = threadIdx.x;
    const int lane = tid & 31;
    const int wid  = tid >> 5;

    int carry = 0;
    for (int base = 0; base < n; base += 1024) {
        int i = base + tid;
        int v = (i < n) ? cnt[i] : 0;
        int s = v;
#pragma unroll
        for (int off = 1; off < 32; off <<= 1) {
            int t = __shfl_up_sync(0xffffffffu, s, off);
            if (lane >= off) s += t;
        }
        if (lane == 31) warp_off[wid] = s;
        __syncthreads();
        if (wid == 0) {
            int wv = warp_off[lane];
            int ws = wv;
#pragma unroll
            for (int off = 1; off < 32; off <<= 1) {
                int t = __shfl_up_sync(0xffffffffu, ws, off);
                if (lane >= off) ws += t;
            }
            warp_off[lane] = ws - wv;
            if (lane == 31) tile_tot = ws;
        }
        __syncthreads();
        int excl = s - v + warp_off[wid] + carry;
        if (i < n) {
            row_start[i] = excl;
            row_next[i]  = excl;
        }
        carry += tile_tot;
        __syncthreads();
    }
    if (tid == 0) row_start[n] = carry;
}

__global__ void scatter_kernel(const int* __restrict__ row, const int* __restrict__ col,
                               const float* __restrict__ vals, int nE,
                               int* __restrict__ row_next, int2* __restrict__ edge)
{
    int i = blockIdx.x * blockDim.x + threadIdx.x;
    if (i < nE) {
        int r = row[i];
        int p = atomicAdd(&row_next[r], 1);
        edge[p] = make_int2(col[i], __float_as_int(vals[i]));
    }
}

// ---------------------------------------------------------------------------
// HMMA primitives
// ---------------------------------------------------------------------------
__device__ __forceinline__ void mma16816(float* d, const uint32_t* a, const uint32_t* b)
{
    asm volatile(
        "mma.sync.aligned.m16n8k16.row.col.f32.f16.f16.f32 "
        "{%0,%1,%2,%3}, {%4,%5,%6,%7}, {%8,%9}, {%0,%1,%2,%3};\n"
        : "+f"(d[0]), "+f"(d[1]), "+f"(d[2]), "+f"(d[3])
        : "r"(a[0]), "r"(a[1]), "r"(a[2]), "r"(a[3]), "r"(b[0]), "r"(b[1]));
}

__device__ __forceinline__ void ldsm_x4(uint32_t* r, uint32_t addr)
{
    asm volatile("ldmatrix.sync.aligned.m8n8.x4.shared.b16 {%0,%1,%2,%3}, [%4];"
                 : "=r"(r[0]), "=r"(r[1]), "=r"(r[2]), "=r"(r[3]) : "r"(addr));
}

__device__ __forceinline__ void ldsm_x4_t(uint32_t* r, uint32_t addr)
{
    asm volatile("ldmatrix.sync.aligned.m8n8.x4.trans.shared.b16 {%0,%1,%2,%3}, [%4];"
                 : "=r"(r[0]), "=r"(r[1]), "=r"(r[2]), "=r"(r[3]) : "r"(addr));
}

#define AS_STRIDE 56
#define WS_STRIDE 136

// ---------------------------------------------------------------------------
// GEMM1 (R4-proven, single buffer): H1 = fp16(X[M,256] @ W1 + b1)
// ---------------------------------------------------------------------------
__global__ __launch_bounds__(256) void gemm1_hmma_kernel(
    const float* __restrict__ A, const float* __restrict__ W,
    const float* __restrict__ bias, __half* __restrict__ C, int M)
{
    constexpr int K = 256, BM = 128, BK = 32, N = 128;
    constexpr int T = K / BK;
    __shared__ __half As[BM * AS_STRIDE];
    __shared__ __half Ws[BK * WS_STRIDE];

    const int tid  = threadIdx.x;
    const int lane = tid & 31;
    const int wid  = tid >> 5;
    const int wm   = wid >> 1;
    const int wn   = wid & 1;
    const int m0   = blockIdx.x * BM;

    float acc[2][8][4];
#pragma unroll
    for (int i = 0; i < 2; i++)
#pragma unroll
        for (int j = 0; j < 8; j++)
#pragma unroll
            for (int q = 0; q < 4; q++) acc[i][j][q] = 0.f;

    const uint32_t sAs = (uint32_t)__cvta_generic_to_shared(As);
    const uint32_t sWs = (uint32_t)__cvta_generic_to_shared(Ws);

    for (int t = 0; t < T; t++) {
        const int k0 = t * BK;
#pragma unroll
        for (int i = 0; i < 4; i++) {
            int idx = tid + i * 256;
            int rr = idx >> 3, cc = (idx & 7) << 2;
            int gr = m0 + rr;
            float4 v = make_float4(0.f, 0.f, 0.f, 0.f);
            if (gr < M) v = *(const float4*)(A + (size_t)gr * K + k0 + cc);
            __half2* dst = (__half2*)(&As[rr * AS_STRIDE + cc]);
            dst[0] = __floats2half2_rn(v.x, v.y);
            dst[1] = __floats2half2_rn(v.z, v.w);
        }
#pragma unroll
        for (int i = 0; i < 4; i++) {
            int idx = tid + i * 256;
            int rr = idx >> 5, cc = (idx & 31) << 2;
            float4 v = *(const float4*)(W + (size_t)(k0 + rr) * N + cc);
            __half2* dst = (__half2*)(&Ws[rr * WS_STRIDE + cc]);
            dst[0] = __floats2half2_rn(v.x, v.y);
            dst[1] = __floats2half2_rn(v.z, v.w);
        }
        __syncthreads();

#pragma unroll
        for (int ks = 0; ks < 2; ks++) {
            const int kk = ks * 16;
            uint32_t a[2][4], b[4][4];
#pragma unroll
            for (int mi = 0; mi < 2; mi++) {
                int r0 = wm * 32 + mi * 16;
                uint32_t addr = sAs + ((r0 + (lane & 15)) * AS_STRIDE
                                       + kk + ((lane >> 4) << 3)) * 2;
                ldsm_x4(a[mi], addr);
            }
#pragma unroll
            for (int p = 0; p < 4; p++) {
                int c0 = wn * 64 + p * 16;
                uint32_t addr = sWs + ((kk + (lane & 15)) * WS_STRIDE
                                       + c0 + ((lane >> 4) << 3)) * 2;
                ldsm_x4_t(b[p], addr);
            }
#pragma unroll
            for (int mi = 0; mi < 2; mi++)
#pragma unroll
                for (int p = 0; p < 4; p++) {
                    mma16816(acc[mi][2 * p],     a[mi], &b[p][0]);
                    mma16816(acc[mi][2 * p + 1], a[mi], &b[p][2]);
                }
        }
        __syncthreads();
    }

    const int rq = lane >> 2;
    const int cq = (lane & 3) << 1;
#pragma unroll
    for (int ni = 0; ni < 8; ni++) {
        int gc = wn * 64 + ni * 8 + cq;
        float2 bb = *(const float2*)(bias + gc);
#pragma unroll
        for (int mi = 0; mi < 2; mi++) {
            int r_base = m0 + wm * 32 + mi * 16 + rq;
            float* d = acc[mi][ni];
            if (r_base < M)
                *(__half2*)(C + (size_t)r_base * N + gc) =
                    __floats2half2_rn(d[0] + bb.x, d[1] + bb.y);
            if (r_base + 8 < M)
                *(__half2*)(C + (size_t)(r_base + 8) * N + gc) =
                    __floats2half2_rn(d[2] + bb.x, d[3] + bb.y);
        }
    }
}

// ---------------------------------------------------------------------------
// FUSED SpMM1 + GEMM2: H2 = fp16( relu(SpMM(A, H1)) @ W2 + b2 )
// Phase A: warp-per-row gather of H1 -> relu -> fp16 A-tile in smem.
// Phase B: HMMA (K=128) over staged A-tile x W2 (staged whole), +b2 -> H2.
// Dynamic smem: 2 * 128 * WS_STRIDE halves = 68 KB.
// ---------------------------------------------------------------------------
__global__ __launch_bounds__(256) void spmm1_gemm2_fused_kernel(
    const int* __restrict__ row_start, const int2* __restrict__ edge,
    const __half* __restrict__ H1, const float* __restrict__ W,
    const float* __restrict__ bias, __half* __restrict__ H2, int M)
{
    constexpr int K = 128, N = 128;
    extern __shared__ __half sm[];
    __half* As = sm;
    __half* Ws = sm + 128 * WS_STRIDE;

    const int tid  = threadIdx.x;
    const int lane = tid & 31;
    const int wid  = tid >> 5;
    const int wm   = wid >> 1;
    const int wn   = wid & 1;
    const int m0   = blockIdx.x * 128;

    // stage W2 (128x128 fp32 -> fp16)
#pragma unroll
    for (int i = 0; i < 16; i++) {
        int idx = tid + i * 256;
        int rr = idx >> 5;
        int cc = (idx & 31) << 2;
        float4 v = *(const float4*)(W + (size_t)rr * N + cc);
        __half2* dst = (__half2*)(&Ws[rr * WS_STRIDE + cc]);
        dst[0] = __floats2half2_rn(v.x, v.y);
        dst[1] = __floats2half2_rn(v.z, v.w);
    }

    // Phase A: gather + relu -> As
    const int fo = lane << 2;
    for (int ri = 0; ri < 16; ri++) {
        int rl = wid * 16 + ri;
        int gr = m0 + rl;
        float4 acc = make_float4(0.f, 0.f, 0.f, 0.f);
        if (gr < M) {
            int s = row_start[gr];
            int e = row_start[gr + 1];
            auto fma_edge = [&](int2 ev) {
                float v = __int_as_float(ev.y);
                uint2 u = *(const uint2*)(H1 + (size_t)ev.x * FEAT + fo);
                float2 h01 = __half22float2(*(const __half2*)&u.x);
                float2 h23 = __half22float2(*(const __half2*)&u.y);
                acc.x += v * h01.x; acc.y += v * h01.y;
                acc.z += v * h23.x; acc.w += v * h23.y;
            };
            int i = s;
            for (; i + 4 <= e; i += 4) {
                int2 e0 = edge[i], e1 = edge[i + 1], e2 = edge[i + 2], e3 = edge[i + 3];
                fma_edge(e0); fma_edge(e1); fma_edge(e2); fma_edge(e3);
            }
            for (; i < e; i++) fma_edge(edge[i]);
        }
        uint2 o;
        *(__half2*)&o.x = __floats2half2_rn(fmaxf(acc.x, 0.f), fmaxf(acc.y, 0.f));
        *(__half2*)&o.y = __floats2half2_rn(fmaxf(acc.z, 0.f), fmaxf(acc.w, 0.f));
        *(uint2*)(&As[rl * WS_STRIDE + fo]) = o;
    }
    __syncthreads();

    // Phase B: HMMA over staged tiles
    float acc[2][8][4];
#pragma unroll
    for (int i = 0; i < 2; i++)
#pragma unroll
        for (int j = 0; j < 8; j++)
#pragma unroll
            for (int q = 0; q < 4; q++) acc[i][j][q] = 0.f;

    const uint32_t sAs = (uint32_t)__cvta_generic_to_shared(As);
    const uint32_t sWs = (uint32_t)__cvta_generic_to_shared(Ws);

#pragma unroll
    for (int ks = 0; ks < K / 16; ks++) {
        const int kk = ks * 16;
        uint32_t a[2][4], b[4][4];
#pragma unroll
        for (int mi = 0; mi < 2; mi++) {
            int r0 = wm * 32 + mi * 16;
            uint32_t addr = sAs + ((r0 + (lane & 15)) * WS_STRIDE
                                   + kk + ((lane >> 4) << 3)) * 2;
            ldsm_x4(a[mi], addr);
        }
#pragma unroll
        for (int p = 0; p < 4; p++) {
            int c0 = wn * 64 + p * 16;
            uint32_t addr = sWs + ((kk + (lane & 15)) * WS_STRIDE
                                   + c0 + ((lane >> 4) << 3)) * 2;
            ldsm_x4_t(b[p], addr);
        }
#pragma unroll
        for (int mi = 0; mi < 2; mi++)
#pragma unroll
            for (int p = 0; p < 4; p++) {
                mma16816(acc[mi][2 * p],     a[mi], &b[p][0]);
                mma16816(acc[mi][2 * p + 1], a[mi], &b[p][2]);
            }
    }

    const int rq = lane >> 2;
    const int cq = (lane & 3) << 1;
#pragma unroll
    for (int ni = 0; ni < 8; ni++) {
        int gc = wn * 64 + ni * 8 + cq;
        float2 bb = *(const float2*)(bias + gc);
#pragma unroll
        for (int mi = 0; mi < 2; mi++) {
            int r_base = m0 + wm * 32 + mi * 16 + rq;
            float* d = acc[mi][ni];
            if (r_base < M)
                *(__half2*)(H2 + (size_t)r_base * N + gc) =
                    __floats2half2_rn(d[0] + bb.x, d[1] + bb.y);
            if (r_base + 8 < M)
                *(__half2*)(H2 + (size_t)(r_base + 8) * N + gc) =
                    __floats2half2_rn(d[2] + bb.x, d[3] + bb.y);
        }
    }
}

// ---------------------------------------------------------------------------
// SpMM2 (R4-proven): warp per row, fp16 gather, fp32 output.
// ---------------------------------------------------------------------------
__global__ __launch_bounds__(256) void spmm2_kernel(
    const int* __restrict__ row_start, const int2* __restrict__ edge,
    const __half* __restrict__ H, float* __restrict__ out, int n)
{
    int r    = blockIdx.x * 8 + (threadIdx.x >> 5);
    int lane = threadIdx.x & 31;
    if (r >= n) return;

    int s = row_start[r];
    int e = row_start[r + 1];

    float4 acc = make_float4(0.f, 0.f, 0.f, 0.f);
    const int fo = lane << 2;

    auto fma_edge = [&](int2 ev) {
        float v = __int_as_float(ev.y);
        uint2 u = *(const uint2*)(H + (size_t)ev.x * FEAT + fo);
        float2 h01 = __half22float2(*(const __half2*)&u.x);
        float2 h23 = __half22float2(*(const __half2*)&u.y);
        acc.x += v * h01.x; acc.y += v * h01.y;
        acc.z += v * h23.x; acc.w += v * h23.y;
    };

    int i = s;
    for (; i + 4 <= e; i += 4) {
        int2 e0 = edge[i], e1 = edge[i + 1], e2 = edge[i + 2], e3 = edge[i + 3];
        fma_edge(e0); fma_edge(e1); fma_edge(e2); fma_edge(e3);
    }
    for (; i < e; i++) fma_edge(edge[i]);

    *(float4*)(out + (size_t)r * FEAT + fo) = acc;
}

// ---------------------------------------------------------------------------
extern "C" void kernel_launch(void* const* d_in, const int* in_sizes, int n_in,
                              void* d_out, int out_size)
{
    const float* X    = (const float*)d_in[0];
    const float* W1   = (const float*)d_in[1];
    const float* b1   = (const float*)d_in[2];
    const float* W2   = (const float*)d_in[3];
    const float* b2   = (const float*)d_in[4];
    const float* vals = (const float*)d_in[5];
    const int*   row  = (const int*)d_in[6];
    const int*   col  = (const int*)d_in[7];

    const int M  = in_sizes[0] / 256;   // 100000
    const int nE = in_sizes[5];         // 1600000

    __half *H1, *H2;
    int *cnt, *row_start, *row_next;
    int2 *edge;
    cudaGetSymbolAddress((void**)&H1,        g_H1);
    cudaGetSymbolAddress((void**)&H2,        g_H2);
    cudaGetSymbolAddress((void**)&cnt,       g_cnt);
    cudaGetSymbolAddress((void**)&row_start, g_row_start);
    cudaGetSymbolAddress((void**)&row_next,  g_row_next);
    cudaGetSymbolAddress((void**)&edge,      g_edge);
    float* out = (float*)d_out;

    const int fused_smem = 2 * 128 * WS_STRIDE * (int)sizeof(__half);  // 69632 B

    static cudaStream_t s_side = nullptr;
    static cudaEvent_t  ev_fork = nullptr, ev_join = nullptr;
    if (s_side == nullptr) {
        cudaStreamCreateWithFlags(&s_side, cudaStreamNonBlocking);
        cudaEventCreateWithFlags(&ev_fork, cudaEventDisableTiming);
        cudaEventCreateWithFlags(&ev_join, cudaEventDisableTiming);
        cudaFuncSetAttribute(spmm1_gemm2_fused_kernel,
                             cudaFuncAttributeMaxDynamicSharedMemorySize, fused_smem);
    }

    // Fork: CSR build on side stream, concurrent with GEMM1.
    cudaEventRecord(ev_fork, 0);
    cudaStreamWaitEvent(s_side, ev_fork, 0);

    const int n4 = (M + 3) / 4;
    zero_cnt_kernel<<<(n4 + 511) / 512, 512, 0, s_side>>>((int4*)cnt, n4);
    hist_kernel<<<(nE + 511) / 512, 512, 0, s_side>>>(row, nE, cnt);
    scan_fused_kernel<<<1, 1024, 0, s_side>>>(cnt, row_start, row_next, M);
    scatter_kernel<<<(nE + 511) / 512, 512, 0, s_side>>>(row, col, vals, nE, row_next, edge);
    cudaEventRecord(ev_join, s_side);

    // Main stream: GEMM1.
    const int gemm_blocks = (M + 127) / 128;
    gemm1_hmma_kernel<<<gemm_blocks, 256>>>(X, W1, b1, H1, M);

    cudaStreamWaitEvent(0, ev_join, 0);
    spmm1_gemm2_fused_kernel<<<gemm_blocks, 256, fused_smem>>>(
        row_start, edge, H1, W2, b2, H2, M);
    spmm2_kernel<<<(M + 7) / 8, 256>>>(row_start, edge, H2, out, M);
}

// round 7
// speedup vs baseline: 1.6581x; 1.6581x over previous
#include <cuda_runtime.h>
#include <cuda_fp16.h>
#include <cstdint>

// ---------------------------------------------------------------------------
// GCN: out = SpMM(relu(SpMM(X@W1+b1)) @ W2 + b2)
// R7: exact R4 components (proven 199.5us) + ONE change: split-M pipeline so
//     GEMM2 of chunk0 overlaps SpMM1 of chunk1 on a second stream.
// ---------------------------------------------------------------------------

#define MAX_NODES 100000
#define MAX_EDGES 1600000
#define FEAT 128
#define SCAN_B 512
#define SCAN_NB ((MAX_NODES + SCAN_B - 1) / SCAN_B)

// Scratch
__device__ __align__(16) __half g_H1[(size_t)MAX_NODES * FEAT];  // GEMM1 out
__device__ __align__(16) __half g_S1[(size_t)MAX_NODES * FEAT];  // relu(SpMM1)
__device__ __align__(16) __half g_H2[(size_t)MAX_NODES * FEAT];  // GEMM2 out
__device__ int  g_cnt[MAX_NODES];
__device__ int  g_row_start[MAX_NODES + 1];
__device__ int  g_row_next[MAX_NODES];
__device__ int  g_partials[SCAN_NB];
__device__ int2 g_edge[MAX_EDGES];

// ---------------------------------------------------------------------------
// CSR build (exact R4)
// ---------------------------------------------------------------------------
__global__ void zero_cnt_kernel(int* __restrict__ cnt, int n)
{
    int i = blockIdx.x * blockDim.x + threadIdx.x;
    if (i < n) cnt[i] = 0;
}

__global__ void hist_kernel(const int* __restrict__ row, int nE, int* __restrict__ cnt)
{
    int i = blockIdx.x * blockDim.x + threadIdx.x;
    if (i < nE) atomicAdd(&cnt[row[i]], 1);
}

__global__ void scan1_kernel(const int* __restrict__ cnt, int* __restrict__ partials, int n)
{
    __shared__ int sh[SCAN_B];
    int i = blockIdx.x * SCAN_B + threadIdx.x;
    sh[threadIdx.x] = (i < n) ? cnt[i] : 0;
    __syncthreads();
#pragma unroll
    for (int off = SCAN_B / 2; off > 0; off >>= 1) {
        if (threadIdx.x < off) sh[threadIdx.x] += sh[threadIdx.x + off];
        __syncthreads();
    }
    if (threadIdx.x == 0) partials[blockIdx.x] = sh[0];
}

__global__ void scan2_kernel(int* __restrict__ partials, int nb,
                             int* __restrict__ row_start, int n)
{
    __shared__ int sh[256];
    int tid = threadIdx.x;
    int v = (tid < nb) ? partials[tid] : 0;
    sh[tid] = v;
    __syncthreads();
#pragma unroll
    for (int off = 1; off < 256; off <<= 1) {
        int t = (tid >= off) ? sh[tid - off] : 0;
        __syncthreads();
        sh[tid] += t;
        __syncthreads();
    }
    if (tid < nb) partials[tid] = sh[tid] - v;
    if (tid == 255) row_start[n] = sh[255];
}

__global__ void scan3_kernel(const int* __restrict__ cnt, const int* __restrict__ partials,
                             int* __restrict__ row_start, int* __restrict__ row_next, int n)
{
    __shared__ int sh[SCAN_B];
    int tid = threadIdx.x;
    int i = blockIdx.x * SCAN_B + tid;
    int v = (i < n) ? cnt[i] : 0;
    sh[tid] = v;
    __syncthreads();
#pragma unroll
    for (int off = 1; off < SCAN_B; off <<= 1) {
        int t = (tid >= off) ? sh[tid - off] : 0;
        __syncthreads();
        sh[tid] += t;
        __syncthreads();
    }
    if (i < n) {
        int excl = sh[tid] - v + partials[blockIdx.x];
        row_start[i] = excl;
        row_next[i]  = excl;
    }
}

__global__ void scatter_kernel(const int* __restrict__ row, const int* __restrict__ col,
                               const float* __restrict__ vals, int nE,
                               int* __restrict__ row_next, int2* __restrict__ edge)
{
    int i = blockIdx.x * blockDim.x + threadIdx.x;
    if (i < nE) {
        int r = row[i];
        int p = atomicAdd(&row_next[r], 1);
        edge[p] = make_int2(col[i], __float_as_int(vals[i]));
    }
}

// ---------------------------------------------------------------------------
// HMMA GEMM (exact R4 kernel + m_base row offset for chunked launches)
// ---------------------------------------------------------------------------
__device__ __forceinline__ void mma16816(float* d, const uint32_t* a, const uint32_t* b)
{
    asm volatile(
        "mma.sync.aligned.m16n8k16.row.col.f32.f16.f16.f32 "
        "{%0,%1,%2,%3}, {%4,%5,%6,%7}, {%8,%9}, {%0,%1,%2,%3};\n"
        : "+f"(d[0]), "+f"(d[1]), "+f"(d[2]), "+f"(d[3])
        : "r"(a[0]), "r"(a[1]), "r"(a[2]), "r"(a[3]), "r"(b[0]), "r"(b[1]));
}

__device__ __forceinline__ void ldsm_x4(uint32_t* r, uint32_t addr)
{
    asm volatile("ldmatrix.sync.aligned.m8n8.x4.shared.b16 {%0,%1,%2,%3}, [%4];"
                 : "=r"(r[0]), "=r"(r[1]), "=r"(r[2]), "=r"(r[3]) : "r"(addr));
}

__device__ __forceinline__ void ldsm_x4_t(uint32_t* r, uint32_t addr)
{
    asm volatile("ldmatrix.sync.aligned.m8n8.x4.trans.shared.b16 {%0,%1,%2,%3}, [%4];"
                 : "=r"(r[0]), "=r"(r[1]), "=r"(r[2]), "=r"(r[3]) : "r"(addr));
}

#define AS_STRIDE 56
#define WS_STRIDE 136

template <int K, bool A_HALF>
__global__ __launch_bounds__(256) void gemm_hmma_kernel(
    const void* __restrict__ A_, const float* __restrict__ W,
    const float* __restrict__ bias, __half* __restrict__ C, int M, int m_base)
{
    constexpr int BM = 128, BK = 32, N = 128;
    constexpr int T = K / BK;
    __shared__ __half As[BM * AS_STRIDE];
    __shared__ __half Ws[BK * WS_STRIDE];

    const int tid  = threadIdx.x;
    const int lane = tid & 31;
    const int wid  = tid >> 5;
    const int wm   = wid >> 1;
    const int wn   = wid & 1;
    const int m0   = m_base + blockIdx.x * BM;

    float acc[2][8][4];
#pragma unroll
    for (int i = 0; i < 2; i++)
#pragma unroll
        for (int j = 0; j < 8; j++)
#pragma unroll
            for (int q = 0; q < 4; q++) acc[i][j][q] = 0.f;

    const uint32_t sAs = (uint32_t)__cvta_generic_to_shared(As);
    const uint32_t sWs = (uint32_t)__cvta_generic_to_shared(Ws);

    for (int t = 0; t < T; t++) {
        const int k0 = t * BK;
        if (A_HALF) {
            const __half* A = (const __half*)A_;
#pragma unroll
            for (int i = 0; i < 2; i++) {
                int idx = tid + i * 256;
                int rr = idx >> 2, cc = (idx & 3) << 3;
                int gr = m0 + rr;
                uint4 v = make_uint4(0, 0, 0, 0);
                if (gr < M) v = *(const uint4*)(A + (size_t)gr * K + k0 + cc);
                *(uint4*)(&As[rr * AS_STRIDE + cc]) = v;
            }
        } else {
            const float* A = (const float*)A_;
#pragma unroll
            for (int i = 0; i < 4; i++) {
                int idx = tid + i * 256;
                int rr = idx >> 3, cc = (idx & 7) << 2;
                int gr = m0 + rr;
                float4 v = make_float4(0.f, 0.f, 0.f, 0.f);
                if (gr < M) v = *(const float4*)(A + (size_t)gr * K + k0 + cc);
                __half2* dst = (__half2*)(&As[rr * AS_STRIDE + cc]);
                dst[0] = __floats2half2_rn(v.x, v.y);
                dst[1] = __floats2half2_rn(v.z, v.w);
            }
        }
#pragma unroll
        for (int i = 0; i < 4; i++) {
            int idx = tid + i * 256;
            int rr = idx >> 5, cc = (idx & 31) << 2;
            float4 v = *(const float4*)(W + (size_t)(k0 + rr) * N + cc);
            __half2* dst = (__half2*)(&Ws[rr * WS_STRIDE + cc]);
            dst[0] = __floats2half2_rn(v.x, v.y);
            dst[1] = __floats2half2_rn(v.z, v.w);
        }
        __syncthreads();

#pragma unroll
        for (int ks = 0; ks < 2; ks++) {
            const int kk = ks * 16;
            uint32_t a[2][4], b[4][4];
#pragma unroll
            for (int mi = 0; mi < 2; mi++) {
                int r0 = wm * 32 + mi * 16;
                uint32_t addr = sAs + ((r0 + (lane & 15)) * AS_STRIDE
                                       + kk + ((lane >> 4) << 3)) * 2;
                ldsm_x4(a[mi], addr);
            }
#pragma unroll
            for (int p = 0; p < 4; p++) {
                int c0 = wn * 64 + p * 16;
                uint32_t addr = sWs + ((kk + (lane & 15)) * WS_STRIDE
                                       + c0 + ((lane >> 4) << 3)) * 2;
                ldsm_x4_t(b[p], addr);
            }
#pragma unroll
            for (int mi = 0; mi < 2; mi++)
#pragma unroll
                for (int p = 0; p < 4; p++) {
                    mma16816(acc[mi][2 * p],     a[mi], &b[p][0]);
                    mma16816(acc[mi][2 * p + 1], a[mi], &b[p][2]);
                }
        }
        __syncthreads();
    }

    const int rq = lane >> 2;
    const int cq = (lane & 3) << 1;
#pragma unroll
    for (int ni = 0; ni < 8; ni++) {
        int gc = wn * 64 + ni * 8 + cq;
        float2 bb = *(const float2*)(bias + gc);
#pragma unroll
        for (int mi = 0; mi < 2; mi++) {
            int r_base = m0 + wm * 32 + mi * 16 + rq;
            float* d = acc[mi][ni];
            if (r_base < M)
                *(__half2*)(C + (size_t)r_base * N + gc) =
                    __floats2half2_rn(d[0] + bb.x, d[1] + bb.y);
            if (r_base + 8 < M)
                *(__half2*)(C + (size_t)(r_base + 8) * N + gc) =
                    __floats2half2_rn(d[2] + bb.x, d[3] + bb.y);
        }
    }
}

// ---------------------------------------------------------------------------
// CSR SpMM (exact R4 kernel + row-range [r0, r_end) for chunked launches)
// ---------------------------------------------------------------------------
template <bool OUT_HALF_RELU>
__global__ __launch_bounds__(256) void spmm_csr_kernel(
    const int* __restrict__ row_start, const int2* __restrict__ edge,
    const __half* __restrict__ H, void* __restrict__ out_, int r0, int r_end)
{
    int r    = r0 + blockIdx.x * 8 + (threadIdx.x >> 5);
    int lane = threadIdx.x & 31;
    if (r >= r_end) return;

    int s = row_start[r];
    int e = row_start[r + 1];

    float4 acc = make_float4(0.f, 0.f, 0.f, 0.f);
    const int fo = lane << 2;

    auto fma_edge = [&](int2 ev) {
        float v = __int_as_float(ev.y);
        uint2 u = *(const uint2*)(H + (size_t)ev.x * FEAT + fo);
        float2 h01 = __half22float2(*(const __half2*)&u.x);
        float2 h23 = __half22float2(*(const __half2*)&u.y);
        acc.x += v * h01.x; acc.y += v * h01.y;
        acc.z += v * h23.x; acc.w += v * h23.y;
    };

    int i = s;
    for (; i + 4 <= e; i += 4) {
        int2 e0 = edge[i], e1 = edge[i + 1], e2 = edge[i + 2], e3 = edge[i + 3];
        fma_edge(e0); fma_edge(e1); fma_edge(e2); fma_edge(e3);
    }
    for (; i < e; i++) fma_edge(edge[i]);

    if (OUT_HALF_RELU) {
        __half* out = (__half*)out_;
        uint2 o;
        *(__half2*)&o.x = __floats2half2_rn(fmaxf(acc.x, 0.f), fmaxf(acc.y, 0.f));
        *(__half2*)&o.y = __floats2half2_rn(fmaxf(acc.z, 0.f), fmaxf(acc.w, 0.f));
        *(uint2*)(out + (size_t)r * FEAT + fo) = o;
    } else {
        float* out = (float*)out_;
        *(float4*)(out + (size_t)r * FEAT + fo) = acc;
    }
}

// ---------------------------------------------------------------------------
extern "C" void kernel_launch(void* const* d_in, const int* in_sizes, int n_in,
                              void* d_out, int out_size)
{
    const float* X    = (const float*)d_in[0];
    const float* W1   = (const float*)d_in[1];
    const float* b1   = (const float*)d_in[2];
    const float* W2   = (const float*)d_in[3];
    const float* b2   = (const float*)d_in[4];
    const float* vals = (const float*)d_in[5];
    const int*   row  = (const int*)d_in[6];
    const int*   col  = (const int*)d_in[7];

    const int M  = in_sizes[0] / 256;   // 100000
    const int nE = in_sizes[5];         // 1600000

    __half *H1, *S1, *H2;
    int *cnt, *row_start, *row_next, *partials;
    int2 *edge;
    cudaGetSymbolAddress((void**)&H1,        g_H1);
    cudaGetSymbolAddress((void**)&S1,        g_S1);
    cudaGetSymbolAddress((void**)&H2,        g_H2);
    cudaGetSymbolAddress((void**)&cnt,       g_cnt);
    cudaGetSymbolAddress((void**)&row_start, g_row_start);
    cudaGetSymbolAddress((void**)&row_next,  g_row_next);
    cudaGetSymbolAddress((void**)&partials,  g_partials);
    cudaGetSymbolAddress((void**)&edge,      g_edge);
    float* out = (float*)d_out;

    static cudaStream_t s_side = nullptr;
    static cudaEvent_t  ev_fork = nullptr, ev_join = nullptr, evA = nullptr, evC = nullptr;
    if (s_side == nullptr) {
        cudaStreamCreateWithFlags(&s_side, cudaStreamNonBlocking);
        cudaEventCreateWithFlags(&ev_fork, cudaEventDisableTiming);
        cudaEventCreateWithFlags(&ev_join, cudaEventDisableTiming);
        cudaEventCreateWithFlags(&evA,     cudaEventDisableTiming);
        cudaEventCreateWithFlags(&evC,     cudaEventDisableTiming);
    }

    const int nb = (M + SCAN_B - 1) / SCAN_B;

    // ---- Fork: CSR build on side stream, concurrent with GEMM1 ----
    cudaEventRecord(ev_fork, 0);
    cudaStreamWaitEvent(s_side, ev_fork, 0);

    zero_cnt_kernel<<<(M + 511) / 512, 512, 0, s_side>>>(cnt, M);
    hist_kernel<<<(nE + 511) / 512, 512, 0, s_side>>>(row, nE, cnt);
    scan1_kernel<<<nb, SCAN_B, 0, s_side>>>(cnt, partials, M);
    scan2_kernel<<<1, 256, 0, s_side>>>(partials, nb, row_start, M);
    scan3_kernel<<<nb, SCAN_B, 0, s_side>>>(cnt, partials, row_start, row_next, M);
    scatter_kernel<<<(nE + 511) / 512, 512, 0, s_side>>>(row, col, vals, nE, row_next, edge);
    cudaEventRecord(ev_join, s_side);

    // ---- GEMM1 on main (concurrent with CSR build) ----
    const int gemm_blocks_full = (M + 127) / 128;
    gemm_hmma_kernel<256, false><<<gemm_blocks_full, 256>>>(X, W1, b1, H1, M, 0);

    cudaStreamWaitEvent(0, ev_join, 0);

    // ---- Split-M pipeline: SpMM1 -> GEMM2, chunk0's GEMM2 overlaps chunk1's SpMM1 ----
    const int M0 = 50048;                        // multiple of 128 and 8
    const int spmm_b0 = M0 / 8;                  // 6256
    const int spmm_b1 = (M - M0 + 7) / 8;        // 6244
    const int gemm_b0 = M0 / 128;                // 391
    const int gemm_b1 = (M - M0 + 127) / 128;    // 391

    // main: SpMM1 chunk0
    spmm_csr_kernel<true><<<spmm_b0, 256>>>(row_start, edge, H1, S1, 0, M0);
    cudaEventRecord(evA, 0);

    // side: GEMM2 chunk0 (waits SpMM1 chunk0) — concurrent with SpMM1 chunk1
    cudaStreamWaitEvent(s_side, evA, 0);
    gemm_hmma_kernel<128, true><<<gemm_b0, 256, 0, s_side>>>(S1, W2, b2, H2, M, 0);
    cudaEventRecord(evC, s_side);

    // main: SpMM1 chunk1, then GEMM2 chunk1
    spmm_csr_kernel<true><<<spmm_b1, 256>>>(row_start, edge, H1, S1, M0, M);
    gemm_hmma_kernel<128, true><<<gemm_b1, 256>>>(S1, W2, b2, H2, M, M0);

    // join: SpMM2 needs all of H2
    cudaStreamWaitEvent(0, evC, 0);
    spmm_csr_kernel<false><<<(M + 7) / 8, 256>>>(row_start, edge, H2, out, 0, M);
}